// round 4
// baseline (speedup 1.0000x reference)
#include <cuda_runtime.h>
#include <stdint.h>

#define QPB   8          // queries per block (1 per warp)
#define CAP   256        // candidate buffer per query
#define KMAX  32
#define MMAX  32768
#define GC    27         // grid cells per axis (1728/64)
#define NC    (GC*GC*GC) // 19683
#define CSH   6          // log2(cell size 64)
#define BCAP  32         // bucket capacity per cell

// ---- device scratch (no allocs allowed) ----
__device__ int   g_cellcnt[NC];
__device__ uint2 g_pts[NC * BCAP];   // bucketed: .x = x|y<<16, .y = z|idx<<16
__device__ int   g_ovcnt;
__device__ uint2 g_ov[MMAX];         // overflow (exactness fallback; empty in practice)

__device__ __forceinline__ int cell_of(int x, int y, int z) {
    return (x >> CSH) + GC * (y >> CSH) + GC * GC * (z >> CSH);
}

__global__ void reset_kernel() {
    int i = blockIdx.x * blockDim.x + threadIdx.x;
    if (i < NC) g_cellcnt[i] = 0;
    if (i == 0) g_ovcnt = 0;
}

__global__ void build_kernel(const int* __restrict__ mid, const int* __restrict__ low,
                             int M1, int M) {
    int i = blockIdx.x * blockDim.x + threadIdx.x;
    if (i >= M) return;
    const int* s = (i < M1) ? (mid + 3 * i) : (low + 3 * (i - M1));
    int x = s[0], y = s[1], z = s[2];
    int c = cell_of(x, y, z);
    uint2 pt = make_uint2((unsigned)x | ((unsigned)y << 16),
                          (unsigned)z | ((unsigned)i << 16));
    int pos = atomicAdd(&g_cellcnt[c], 1);
    if (pos < BCAP) g_pts[c * BCAP + pos] = pt;
    else            g_ov[atomicAdd(&g_ovcnt, 1)] = pt;
}

// Exact k-th select (binary search on integer d2 < 2^24), then compact entries
// with d2 <= T to front. Returns T; updates cnt (warp-uniform). Keeps ties.
__device__ __forceinline__ int warp_prune(uint2* buf, int& cnt, int k, int lane) {
    unsigned d2r[CAP / 32], idr[CAP / 32];
#pragma unroll
    for (int s = 0; s < CAP / 32; s++) {
        int i = s * 32 + lane;
        uint2 e = (i < cnt) ? buf[i] : make_uint2(0x7fffffffu, 0u);
        d2r[s] = e.x; idr[s] = e.y;
    }
    unsigned lo = 0, hi = 0x00ffffffu;
    while (lo < hi) {
        unsigned mid = (lo + hi) >> 1;
        int c = 0;
#pragma unroll
        for (int s = 0; s < CAP / 32; s++) c += (d2r[s] <= mid) ? 1 : 0;
        c = __reduce_add_sync(0xffffffffu, c);
        if (c >= k) hi = mid; else lo = mid + 1;
    }
    unsigned T = lo;
    int base = 0;
#pragma unroll
    for (int s = 0; s < CAP / 32; s++) {
        bool keep = (d2r[s] <= T);
        unsigned m = __ballot_sync(0xffffffffu, keep);
        int pos = base + __popc(m & ((1u << lane) - 1u));
        if (keep && pos < CAP) buf[pos] = make_uint2(d2r[s], idr[s]);
        base += __popc(m);
    }
    __syncwarp();
    cnt = (base < CAP) ? base : CAP;
    return (int)T;
}

// Scan points of the (<=32) cells owned by lanes: lane i walks its own bucket.
// ccnt/cbase per-lane. Unroll-by-4 loads for MLP. Updates cnt and T.
__device__ __forceinline__ void scan_cells(int ccnt, int cbase,
                                           int qx, int qy, int qz,
                                           uint2* bufrow, int& cnt, int& T,
                                           int kk, int lane, unsigned lmlt) {
    const unsigned FULL = 0xffffffffu;
    int mx = __reduce_max_sync(FULL, ccnt);
    for (int t = 0; t < mx; t += 4) {
        uint2 p[4];
        bool  v[4];
#pragma unroll
        for (int u = 0; u < 4; u++) {
            v[u] = (t + u < ccnt);
            if (v[u]) p[u] = g_pts[cbase + t + u];
        }
        int      d2[4];
        unsigned pidx[4];
#pragma unroll
        for (int u = 0; u < 4; u++) {
            if (v[u]) {
                int dx = qx - (int)(p[u].x & 0xffffu);
                int dy = qy - (int)(p[u].x >> 16);
                int dz = qz - (int)(p[u].y & 0xffffu);
                d2[u] = dx * dx + dy * dy + dz * dz;
                pidx[u] = p[u].y >> 16;
            }
        }
#pragma unroll
        for (int u = 0; u < 4; u++) {
            bool hit = v[u] && (d2[u] <= T);
            unsigned m = __ballot_sync(FULL, hit);
            int pos = cnt + __popc(m & lmlt);
            if (hit && pos < CAP) bufrow[pos] = make_uint2((unsigned)d2[u], pidx[u]);
            cnt += __popc(m);
        }
        if (cnt > CAP - 128) T = warp_prune(bufrow, cnt, kk, lane);
    }
}

__global__ __launch_bounds__(256)
void knn_query_kernel(const int* __restrict__ qc,
                      const float* __restrict__ midf,
                      const float* __restrict__ lowf,
                      const int* __restrict__ kp,
                      float* __restrict__ out,
                      int N, int M1, int D) {
    __shared__ uint2    s_buf[QPB][CAP];
    __shared__ int      s_selidx[QPB][KMAX];
    __shared__ unsigned s_seld2[QPB][KMAX];
    __shared__ float    s_wt[QPB][KMAX];

    const unsigned FULL = 0xffffffffu;
    const int tid = threadIdx.x;
    const int w = tid >> 5;
    const int lane = tid & 31;
    const unsigned lmlt = (1u << lane) - 1u;
    const int kk = kp ? min(*kp, KMAX) : 24;

    const int q = blockIdx.x * QPB + w;
    if (q >= N) return;                         // whole warp exits together

    const int qx = qc[3 * q], qy = qc[3 * q + 1], qz = qc[3 * q + 2];
    const int qcx = min(qx >> CSH, GC - 1);
    const int qcy = min(qy >> CSH, GC - 1);
    const int qcz = min(qz >> CSH, GC - 1);

    int cnt = 0;
    int T = 0x7fffffff;

    // ---- overflow fallback (empty unless some bucket spilled) ----
    const int ov = g_ovcnt;
    for (int b = 0; b < ov; b += 32) {
        int i = b + lane;
        bool valid = (i < ov);
        int d2 = 0; unsigned pidx = 0;
        if (valid) {
            uint2 p = g_ov[i];
            int dx = qx - (int)(p.x & 0xffffu);
            int dy = qy - (int)(p.x >> 16);
            int dz = qz - (int)(p.y & 0xffffu);
            d2 = dx * dx + dy * dy + dz * dz;
            pidx = p.y >> 16;
        }
        bool hit = valid && (d2 <= T);
        unsigned m = __ballot_sync(FULL, hit);
        int pos = cnt + __popc(m & lmlt);
        if (hit && pos < CAP) s_buf[w][pos] = make_uint2((unsigned)d2, pidx);
        cnt += __popc(m);
        if (cnt > CAP - 32) T = warp_prune(&s_buf[w][0], cnt, kk, lane);
    }

    // ---- combined first shell: all 27 cells with cheb <= 1, one lane-batch ----
    {
        int ccnt = 0, cbase = 0;
        if (lane < 27) {
            int di = lane % 3 - 1;
            int dj = (lane / 3) % 3 - 1;
            int dk = lane / 9 - 1;
            int ci = qcx + di, cj = qcy + dj, ck = qcz + dk;
            if (ci >= 0 && ci < GC && cj >= 0 && cj < GC && ck >= 0 && ck < GC) {
                int cell = ci + GC * cj + GC * GC * ck;
                ccnt = min(g_cellcnt[cell], BCAP);
                cbase = cell * BCAP;
            }
        }
        scan_cells(ccnt, cbase, qx, qy, qz, &s_buf[w][0], cnt, T, kk, lane, lmlt);
    }
    bool done = false;
    if (cnt >= kk) {
        T = warp_prune(&s_buf[w][0], cnt, kk, lane);
        done = ((1 << CSH) * (1 << CSH) >= T);   // shell >=2 min dist > 64
    }

    // ---- expanding shells s >= 2 ----
    for (int s = 2; s < GC && !done; s++) {
        const int side = 2 * s + 1;
        const int ncube = side * side * side;
        for (int b = 0; b < ncube; b += 32) {
            int t = b + lane;
            int ccnt = 0, cbase = 0;
            if (t < ncube) {
                int di = t % side - s;
                int r1 = t / side;
                int dj = r1 % side - s;
                int dk = r1 / side - s;
                int cheb = max(abs(di), max(abs(dj), abs(dk)));
                int ci = qcx + di, cj = qcy + dj, ck = qcz + dk;
                if (cheb == s && ci >= 0 && ci < GC && cj >= 0 && cj < GC
                               && ck >= 0 && ck < GC) {
                    int lx = ci << CSH, ly = cj << CSH, lz = ck << CSH;
                    int mdx = max(0, max(lx - qx, qx - (lx + 63)));
                    int mdy = max(0, max(ly - qy, qy - (ly + 63)));
                    int mdz = max(0, max(lz - qz, qz - (lz + 63)));
                    int md2 = mdx * mdx + mdy * mdy + mdz * mdz;
                    if (md2 <= T) {
                        int cell = ci + GC * cj + GC * GC * ck;
                        ccnt = min(g_cellcnt[cell], BCAP);
                        cbase = cell * BCAP;
                    }
                }
            }
            scan_cells(ccnt, cbase, qx, qy, qz, &s_buf[w][0], cnt, T, kk, lane, lmlt);
        }
        if (cnt >= kk) {
            T = warp_prune(&s_buf[w][0], cnt, kk, lane);
            int bnd = s << CSH;                  // shell s+1 min dist > s*64
            if (bnd * bnd >= T) done = true;
        }
    }

    // ----- final exact top-k by composite key (d2, idx): stable ties -----
    const int kk2 = min(kk, cnt);
    {
        unsigned d2r[CAP / 32], idr[CAP / 32];
        unsigned long long keyr[CAP / 32];
        int rk[CAP / 32];
#pragma unroll
        for (int s = 0; s < CAP / 32; s++) {
            int i = s * 32 + lane;
            uint2 e = (i < cnt) ? s_buf[w][i] : make_uint2(0xffffffffu, 0xffffffffu);
            d2r[s] = e.x; idr[s] = e.y;
            keyr[s] = ((unsigned long long)e.x << 32) | (unsigned long long)e.y;
            rk[s] = 0;
        }
        for (int jj = 0; jj < cnt; jj++) {
            uint2 ej = s_buf[w][jj];            // uniform addr: LDS broadcast
            unsigned long long kj = ((unsigned long long)ej.x << 32)
                                  | (unsigned long long)ej.y;
#pragma unroll
            for (int s = 0; s < CAP / 32; s++) rk[s] += (kj < keyr[s]) ? 1 : 0;
        }
#pragma unroll
        for (int s = 0; s < CAP / 32; s++) {
            int i = s * 32 + lane;
            if (i < cnt && rk[s] < kk2) {
                s_selidx[w][rk[s]] = (int)idr[s];
                s_seld2[w][rk[s]]  = d2r[s];
            }
        }
        __syncwarp();
    }

    float wj = 0.0f;
    if (lane < kk2) wj = 1.0f / (1.0f + sqrtf((float)s_seld2[w][lane]));
    float tot = wj;
#pragma unroll
    for (int o = 16; o > 0; o >>= 1) tot += __shfl_xor_sync(FULL, tot, o);
    if (lane < kk2) s_wt[w][lane] = wj / tot;
    __syncwarp();

    // ----- weighted feature gather -----
    if (D == 128) {
        float4 acc = make_float4(0.f, 0.f, 0.f, 0.f);
        for (int j = 0; j < kk2; j++) {
            int   si = s_selidx[w][j];
            float wt = s_wt[w][j];
            const float* f = (si < M1) ? (midf + (size_t)si * 128)
                                       : (lowf + (size_t)(si - M1) * 128);
            float4 v = *(const float4*)(f + lane * 4);
            acc.x += wt * v.x; acc.y += wt * v.y;
            acc.z += wt * v.z; acc.w += wt * v.w;
        }
        *(float4*)(out + (size_t)q * 128 + lane * 4) = acc;
    } else {
        for (int d = lane; d < D; d += 32) {
            float a = 0.f;
            for (int j = 0; j < kk2; j++) {
                int   si = s_selidx[w][j];
                float wt = s_wt[w][j];
                const float* f = (si < M1) ? (midf + (size_t)si * D)
                                           : (lowf + (size_t)(si - M1) * D);
                a += wt * f[d];
            }
            out[(size_t)q * D + d] = a;
        }
    }
}

extern "C" void kernel_launch(void* const* d_in, const int* in_sizes, int n_in,
                              void* d_out, int out_size) {
    const int*   qc   = (const int*)d_in[0];
    const int*   midc = (const int*)d_in[1];
    const int*   lowc = (const int*)d_in[2];
    const float* midf = (const float*)d_in[3];
    const float* lowf = (const float*)d_in[4];
    const int*   kp   = (n_in >= 6) ? (const int*)d_in[5] : nullptr;

    const int N  = in_sizes[0] / 3;
    const int M1 = in_sizes[1] / 3;
    const int M2 = in_sizes[2] / 3;
    const int M  = M1 + M2;
    const int D  = (M1 > 0) ? in_sizes[3] / M1 : 128;

    reset_kernel<<<(NC + 255) / 256, 256>>>();
    build_kernel<<<(M + 255) / 256, 256>>>(midc, lowc, M1, M);
    knn_query_kernel<<<(N + QPB - 1) / QPB, 256>>>(qc, midf, lowf, kp,
                                                   (float*)d_out, N, M1, D);
}

// round 5
// speedup vs baseline: 1.3060x; 1.3060x over previous
#include <cuda_runtime.h>
#include <stdint.h>

#define QPB   8          // queries per block (1 per warp)
#define CAP   192        // candidate buffer per query
#define KMAX  32
#define MMAX  32768
#define GC    27         // grid cells per axis (1728/64)
#define NC    (GC*GC*GC) // 19683
#define CSH   6          // log2(cell size 64)
#define BCAP  32         // bucket capacity per cell

// ---- device scratch (no allocs allowed) ----
struct Scratch {
    int ovcnt;
    int cellcnt[NC];
};
__device__ Scratch g_scr;            // zeroed by one cudaMemsetAsync per call
__device__ uint2 g_pts[NC * BCAP];   // bucketed: .x = x|y<<16, .y = z|idx<<16
__device__ uint2 g_ov[MMAX];         // overflow (exactness fallback; empty in practice)

__device__ __forceinline__ int cell_of(int x, int y, int z) {
    return (x >> CSH) + GC * (y >> CSH) + GC * GC * (z >> CSH);
}

__global__ void build_kernel(const int* __restrict__ mid, const int* __restrict__ low,
                             int M1, int M) {
    int i = blockIdx.x * blockDim.x + threadIdx.x;
    if (i >= M) return;
    const int* s = (i < M1) ? (mid + 3 * i) : (low + 3 * (i - M1));
    int x = s[0], y = s[1], z = s[2];
    int c = cell_of(x, y, z);
    uint2 pt = make_uint2((unsigned)x | ((unsigned)y << 16),
                          (unsigned)z | ((unsigned)i << 16));
    int pos = atomicAdd(&g_scr.cellcnt[c], 1);
    if (pos < BCAP) g_pts[c * BCAP + pos] = pt;
    else            g_ov[atomicAdd(&g_scr.ovcnt, 1)] = pt;
}

// Exact k-th select (binary search on integer d2), then compact entries with
// d2 <= T to front. Returns T; updates cnt (warp-uniform). Keeps all ties.
__device__ __forceinline__ int warp_prune(uint2* buf, int& cnt, int k, int lane) {
    const unsigned FULL = 0xffffffffu;
    unsigned d2r[CAP / 32], idr[CAP / 32];
#pragma unroll
    for (int s = 0; s < CAP / 32; s++) {
        int i = s * 32 + lane;
        uint2 e = (i < cnt) ? buf[i] : make_uint2(0x7fffffffu, 0u);
        d2r[s] = e.x; idr[s] = e.y;
    }
    // hi bound = max d2 actually present (shrinks the search range)
    unsigned mx = 0;
#pragma unroll
    for (int s = 0; s < CAP / 32; s++) {
        int i = s * 32 + lane;
        if (i < cnt) mx = max(mx, d2r[s]);
    }
    unsigned lo = 0, hi = __reduce_max_sync(FULL, mx);
    while (lo < hi) {
        unsigned mid = (lo + hi) >> 1;
        int c = 0;
#pragma unroll
        for (int s = 0; s < CAP / 32; s++) c += (d2r[s] <= mid) ? 1 : 0;
        c = __reduce_add_sync(FULL, c);
        if (c >= k) hi = mid; else lo = mid + 1;
    }
    unsigned T = lo;
    int base = 0;
#pragma unroll
    for (int s = 0; s < CAP / 32; s++) {
        bool keep = (d2r[s] <= T);
        unsigned m = __ballot_sync(FULL, keep);
        if (keep) buf[base + __popc(m & ((1u << lane) - 1u))] = make_uint2(d2r[s], idr[s]);
        base += __popc(m);
    }
    __syncwarp();
    cnt = base;
    return (int)T;
}

__global__ __launch_bounds__(256)
void knn_query_kernel(const int* __restrict__ qc,
                      const float* __restrict__ midf,
                      const float* __restrict__ lowf,
                      const int* __restrict__ kp,
                      float* __restrict__ out,
                      int N, int M1, int D) {
    __shared__ uint2    s_buf[QPB][CAP];
    __shared__ int      s_base[QPB][32];
    __shared__ int      s_pref[QPB][33];
    __shared__ int      s_selidx[QPB][KMAX];
    __shared__ unsigned s_seld2[QPB][KMAX];
    __shared__ float    s_wt[QPB][KMAX];

    const unsigned FULL = 0xffffffffu;
    const int tid = threadIdx.x;
    const int w = tid >> 5;
    const int lane = tid & 31;
    const unsigned lmlt = (1u << lane) - 1u;
    const int kk = kp ? min(*kp, KMAX) : 24;

    const int q = blockIdx.x * QPB + w;
    if (q >= N) return;                         // whole warp exits together

    const int qx = qc[3 * q], qy = qc[3 * q + 1], qz = qc[3 * q + 2];
    const int qcx = min(qx >> CSH, GC - 1);
    const int qcy = min(qy >> CSH, GC - 1);
    const int qcz = min(qz >> CSH, GC - 1);

    int cnt = 0;
    int T = 0x7fffffff;

    // ---- overflow fallback (empty unless some bucket spilled) ----
    const int ov = g_scr.ovcnt;
    for (int b = 0; b < ov; b += 32) {
        int i = b + lane;
        bool valid = (i < ov);
        int d2 = 0; unsigned pidx = 0;
        if (valid) {
            uint2 p = g_ov[i];
            int dx = qx - (int)(p.x & 0xffffu);
            int dy = qy - (int)(p.x >> 16);
            int dz = qz - (int)(p.y & 0xffffu);
            d2 = dx * dx + dy * dy + dz * dz;
            pidx = p.y >> 16;
        }
        bool hit = valid && (d2 <= T);
        unsigned m = __ballot_sync(FULL, hit);
        if (hit) s_buf[w][cnt + __popc(m & lmlt)] = make_uint2((unsigned)d2, pidx);
        cnt += __popc(m);
        if (cnt > CAP - 32) T = warp_prune(&s_buf[w][0], cnt, kk, lane);
    }

    // ==== cell-batch processing: lane -> cell, balanced segment-union scan ====
    // Stages: (A) combined cheb<=1 pass (27 cells, one batch), (B) shells s>=2.
    bool done = false;
    for (int s = 1; s < GC && !done; s++) {
        const int side = 2 * s + 1;
        const int ncube = side * side * side;
        const bool first = (s == 1);
        for (int b = 0; b < ncube; b += 32) {
            int t = b + lane;
            int ccnt = 0, cbase = 0;
            if (t < ncube) {
                int di = t % side - s;
                int r1 = t / side;
                int dj = r1 % side - s;
                int dk = r1 / side - s;
                int cheb = max(abs(di), max(abs(dj), abs(dk)));
                int ci = qcx + di, cj = qcy + dj, ck = qcz + dk;
                // first pass takes the whole cheb<=1 cube; later shells surface only
                if ((first || cheb == s) && ci >= 0 && ci < GC && cj >= 0 && cj < GC
                                         && ck >= 0 && ck < GC) {
                    int lx = ci << CSH, ly = cj << CSH, lz = ck << CSH;
                    int mdx = max(0, max(lx - qx, qx - (lx + 63)));
                    int mdy = max(0, max(ly - qy, qy - (ly + 63)));
                    int mdz = max(0, max(lz - qz, qz - (lz + 63)));
                    int md2 = mdx * mdx + mdy * mdy + mdz * mdz;
                    if (md2 <= T) {
                        int cell = ci + GC * cj + GC * GC * ck;
                        ccnt = min(g_scr.cellcnt[cell], BCAP);
                        cbase = cell * BCAP;
                    }
                }
            }
            // warp inclusive scan of ccnt
            int inc = ccnt;
#pragma unroll
            for (int off = 1; off < 32; off <<= 1) {
                int v = __shfl_up_sync(FULL, inc, off);
                if (lane >= off) inc += v;
            }
            int P = __shfl_sync(FULL, inc, 31);
            if (P == 0) continue;
            if (lane == 0) s_pref[w][0] = 0;
            s_pref[w][lane + 1] = inc;
            s_base[w][lane] = cbase - (inc - ccnt);   // point = g_pts[base + t2]
            __syncwarp();

            // dual-batched scan: 64 points per iteration, independent LDG pair
            const int nb = (P + 31) >> 5;
            for (int it = 0; it < nb; it += 2) {
                int t2a = it * 32 + lane;
                int t2b = t2a + 32;
                bool va = (t2a < P), vb = (t2b < P);
                int ja = 0, jb = 0;
#pragma unroll
                for (int step = 16; step >= 1; step >>= 1) {
                    if (s_pref[w][ja + step] <= t2a) ja += step;
                    if (s_pref[w][jb + step] <= t2b) jb += step;
                }
                uint2 pa, pb;
                if (va) pa = g_pts[s_base[w][ja] + t2a];
                if (vb) pb = g_pts[s_base[w][jb] + t2b];
                int d2a = 0, d2b = 0;
                unsigned ia = 0, ib = 0;
                if (va) {
                    int dx = qx - (int)(pa.x & 0xffffu);
                    int dy = qy - (int)(pa.x >> 16);
                    int dz = qz - (int)(pa.y & 0xffffu);
                    d2a = dx * dx + dy * dy + dz * dz;
                    ia = pa.y >> 16;
                }
                if (vb) {
                    int dx = qx - (int)(pb.x & 0xffffu);
                    int dy = qy - (int)(pb.x >> 16);
                    int dz = qz - (int)(pb.y & 0xffffu);
                    d2b = dx * dx + dy * dy + dz * dz;
                    ib = pb.y >> 16;
                }
                bool ha = va && (d2a <= T);
                unsigned ma = __ballot_sync(FULL, ha);
                if (ha) s_buf[w][cnt + __popc(ma & lmlt)] = make_uint2((unsigned)d2a, ia);
                cnt += __popc(ma);
                bool hb = vb && (d2b <= T);
                unsigned mb = __ballot_sync(FULL, hb);
                if (hb) s_buf[w][cnt + __popc(mb & lmlt)] = make_uint2((unsigned)d2b, ib);
                cnt += __popc(mb);
                if (cnt > CAP - 64) T = warp_prune(&s_buf[w][0], cnt, kk, lane);
            }
            __syncwarp();
        }
        // stage finished: tighten T, then test provable lower bound of next stage
        if (cnt >= kk) {
            T = warp_prune(&s_buf[w][0], cnt, kk, lane);
            int bnd = s << CSH;                  // next stage min dist > s*64
            if (bnd * bnd >= T) done = true;
        }
    }

    // ----- final exact top-k by composite key (d2, idx): stable ties -----
    const int kk2 = min(kk, cnt);
    {
        unsigned d2r[CAP / 32], idr[CAP / 32];
        unsigned long long keyr[CAP / 32];
        int rk[CAP / 32];
#pragma unroll
        for (int s = 0; s < CAP / 32; s++) {
            int i = s * 32 + lane;
            uint2 e = (i < cnt) ? s_buf[w][i] : make_uint2(0xffffffffu, 0xffffffffu);
            d2r[s] = e.x; idr[s] = e.y;
            keyr[s] = ((unsigned long long)e.x << 32) | (unsigned long long)e.y;
            rk[s] = 0;
        }
        for (int jj = 0; jj < cnt; jj++) {
            uint2 ej = s_buf[w][jj];            // uniform addr: LDS broadcast
            unsigned long long kj = ((unsigned long long)ej.x << 32)
                                  | (unsigned long long)ej.y;
#pragma unroll
            for (int s = 0; s < CAP / 32; s++) rk[s] += (kj < keyr[s]) ? 1 : 0;
        }
#pragma unroll
        for (int s = 0; s < CAP / 32; s++) {
            int i = s * 32 + lane;
            if (i < cnt && rk[s] < kk2) {
                s_selidx[w][rk[s]] = (int)idr[s];
                s_seld2[w][rk[s]]  = d2r[s];
            }
        }
        __syncwarp();
    }

    float wj = 0.0f;
    if (lane < kk2) wj = 1.0f / (1.0f + sqrtf((float)s_seld2[w][lane]));
    float tot = wj;
#pragma unroll
    for (int o = 16; o > 0; o >>= 1) tot += __shfl_xor_sync(FULL, tot, o);
    if (lane < kk2) s_wt[w][lane] = wj / tot;
    __syncwarp();

    // ----- weighted feature gather -----
    if (D == 128) {
        float4 acc = make_float4(0.f, 0.f, 0.f, 0.f);
        for (int j = 0; j < kk2; j++) {
            int   si = s_selidx[w][j];
            float wt = s_wt[w][j];
            const float* f = (si < M1) ? (midf + (size_t)si * 128)
                                       : (lowf + (size_t)(si - M1) * 128);
            float4 v = *(const float4*)(f + lane * 4);
            acc.x += wt * v.x; acc.y += wt * v.y;
            acc.z += wt * v.z; acc.w += wt * v.w;
        }
        *(float4*)(out + (size_t)q * 128 + lane * 4) = acc;
    } else {
        for (int d = lane; d < D; d += 32) {
            float a = 0.f;
            for (int j = 0; j < kk2; j++) {
                int   si = s_selidx[w][j];
                float wt = s_wt[w][j];
                const float* f = (si < M1) ? (midf + (size_t)si * D)
                                           : (lowf + (size_t)(si - M1) * D);
                a += wt * f[d];
            }
            out[(size_t)q * D + d] = a;
        }
    }
}

extern "C" void kernel_launch(void* const* d_in, const int* in_sizes, int n_in,
                              void* d_out, int out_size) {
    const int*   qc   = (const int*)d_in[0];
    const int*   midc = (const int*)d_in[1];
    const int*   lowc = (const int*)d_in[2];
    const float* midf = (const float*)d_in[3];
    const float* lowf = (const float*)d_in[4];
    const int*   kp   = (n_in >= 6) ? (const int*)d_in[5] : nullptr;

    const int N  = in_sizes[0] / 3;
    const int M1 = in_sizes[1] / 3;
    const int M2 = in_sizes[2] / 3;
    const int M  = M1 + M2;
    const int D  = (M1 > 0) ? in_sizes[3] / M1 : 128;

    void* scr = nullptr;
    cudaGetSymbolAddress(&scr, g_scr);             // host query, not a stream op
    cudaMemsetAsync(scr, 0, sizeof(Scratch));      // graph memset node

    build_kernel<<<(M + 255) / 256, 256>>>(midc, lowc, M1, M);
    knn_query_kernel<<<(N + QPB - 1) / QPB, 256>>>(qc, midf, lowf, kp,
                                                   (float*)d_out, N, M1, D);
}

// round 6
// speedup vs baseline: 1.4510x; 1.1110x over previous
#include <cuda_runtime.h>
#include <stdint.h>

#define QPB   8          // queries per block (1 per warp)
#define CAP   320        // candidate buffer per query (first pass unfiltered)
#define KMAX  32
#define MMAX  32768
#define GC    27         // grid cells per axis (1728/64)
#define NC    (GC*GC*GC) // 19683
#define CSH   6          // log2(cell size 64)
#define BCAP  32         // bucket capacity per cell

// ---- device scratch (no allocs allowed) ----
struct Scratch {
    int ovcnt;
    int cellcnt[NC];
};
__device__ Scratch g_scr;            // zeroed by one cudaMemsetAsync per call
__device__ uint2 g_pts[NC * BCAP];   // bucketed: .x = x|y<<16, .y = z|idx<<16
__device__ uint2 g_ov[MMAX];         // overflow (exactness fallback; empty in practice)

__device__ __forceinline__ int cell_of(int x, int y, int z) {
    return (x >> CSH) + GC * (y >> CSH) + GC * GC * (z >> CSH);
}

__global__ void build_kernel(const int* __restrict__ mid, const int* __restrict__ low,
                             int M1, int M) {
    int i = blockIdx.x * blockDim.x + threadIdx.x;
    if (i >= M) return;
    const int* s = (i < M1) ? (mid + 3 * i) : (low + 3 * (i - M1));
    int x = s[0], y = s[1], z = s[2];
    int c = cell_of(x, y, z);
    uint2 pt = make_uint2((unsigned)x | ((unsigned)y << 16),
                          (unsigned)z | ((unsigned)i << 16));
    int pos = atomicAdd(&g_scr.cellcnt[c], 1);
    if (pos < BCAP) g_pts[c * BCAP + pos] = pt;
    else            g_ov[atomicAdd(&g_scr.ovcnt, 1)] = pt;
}

// Exact k-th select (binary search on integer d2), then compact entries with
// d2 <= T to front. Returns T; updates cnt (warp-uniform). Keeps all ties.
__device__ __forceinline__ int warp_prune(uint2* buf, int& cnt, int k, int lane) {
    const unsigned FULL = 0xffffffffu;
    unsigned d2r[CAP / 32], idr[CAP / 32];
#pragma unroll
    for (int s = 0; s < CAP / 32; s++) {
        int i = s * 32 + lane;
        uint2 e = (i < cnt) ? buf[i] : make_uint2(0x7fffffffu, 0u);
        d2r[s] = e.x; idr[s] = e.y;
    }
    unsigned mx = 0;
#pragma unroll
    for (int s = 0; s < CAP / 32; s++) {
        int i = s * 32 + lane;
        if (i < cnt) mx = max(mx, d2r[s]);
    }
    unsigned lo = 0, hi = __reduce_max_sync(FULL, mx);
    while (lo < hi) {
        unsigned mid = (lo + hi) >> 1;
        int c = 0;
#pragma unroll
        for (int s = 0; s < CAP / 32; s++) c += (d2r[s] <= mid) ? 1 : 0;
        c = __reduce_add_sync(FULL, c);
        if (c >= k) hi = mid; else lo = mid + 1;
    }
    unsigned T = lo;
    int base = 0;
#pragma unroll
    for (int s = 0; s < CAP / 32; s++) {
        bool keep = (d2r[s] <= T);
        unsigned m = __ballot_sync(FULL, keep);
        if (keep) buf[base + __popc(m & ((1u << lane) - 1u))] = make_uint2(d2r[s], idr[s]);
        base += __popc(m);
    }
    __syncwarp();
    cnt = base;
    return (int)T;
}

__global__ __launch_bounds__(256)
void knn_query_kernel(const int* __restrict__ qc,
                      const float* __restrict__ midf,
                      const float* __restrict__ lowf,
                      const int* __restrict__ kp,
                      float* __restrict__ out,
                      int N, int M1, int D) {
    __shared__ uint2    s_buf[QPB][CAP];
    __shared__ int      s_base[QPB][32];
    __shared__ int      s_pref[QPB][33];
    __shared__ int      s_selidx[QPB][KMAX];
    __shared__ unsigned s_seld2[QPB][KMAX];
    __shared__ float    s_wt[QPB][KMAX];

    const unsigned FULL = 0xffffffffu;
    const int tid = threadIdx.x;
    const int w = tid >> 5;
    const int lane = tid & 31;
    const unsigned lmlt = (1u << lane) - 1u;
    const int kk = kp ? min(*kp, KMAX) : 24;

    const int q = blockIdx.x * QPB + w;
    if (q >= N) return;                         // whole warp exits together

    const int qx = qc[3 * q], qy = qc[3 * q + 1], qz = qc[3 * q + 2];
    const int qcx = min(qx >> CSH, GC - 1);
    const int qcy = min(qy >> CSH, GC - 1);
    const int qcz = min(qz >> CSH, GC - 1);

    const int NEAR2 = (1 << CSH) * (1 << CSH);  // 4096: shell>=2 min d2 strictly exceeds this

    int cnt = 0;
    int T = 0x7fffffff;

    // ---- overflow fallback (empty unless some bucket spilled) ----
    const int ov = g_scr.ovcnt;
    for (int b = 0; b < ov; b += 32) {
        int i = b + lane;
        bool valid = (i < ov);
        int d2 = 0; unsigned pidx = 0;
        if (valid) {
            uint2 p = g_ov[i];
            int dx = qx - (int)(p.x & 0xffffu);
            int dy = qy - (int)(p.x >> 16);
            int dz = qz - (int)(p.y & 0xffffu);
            d2 = dx * dx + dy * dy + dz * dz;
            pidx = p.y >> 16;
        }
        bool hit = valid && (d2 <= T);
        unsigned m = __ballot_sync(FULL, hit);
        if (hit) s_buf[w][cnt + __popc(m & lmlt)] = make_uint2((unsigned)d2, pidx);
        cnt += __popc(m);
        if (cnt > CAP - 32) T = warp_prune(&s_buf[w][0], cnt, kk, lane);
    }

    // ==== stages: (s=1) full cheb<=1 cube (27 cells); (s>=2) shell surfaces ====
    bool done = false;
    for (int s = 1; s < GC && !done; s++) {
        const int side = 2 * s + 1;
        const int ncube = side * side * side;
        const bool first = (s == 1);
        int nearc = 0;                         // hits with d2 <= NEAR2 (first pass)
        for (int b = 0; b < ncube; b += 32) {
            int t = b + lane;
            int ccnt = 0, cbase = 0;
            if (t < ncube) {
                int di = t % side - s;
                int r1 = t / side;
                int dj = r1 % side - s;
                int dk = r1 / side - s;
                int cheb = max(abs(di), max(abs(dj), abs(dk)));
                int ci = qcx + di, cj = qcy + dj, ck = qcz + dk;
                if ((first || cheb == s) && ci >= 0 && ci < GC && cj >= 0 && cj < GC
                                         && ck >= 0 && ck < GC) {
                    int lx = ci << CSH, ly = cj << CSH, lz = ck << CSH;
                    int mdx = max(0, max(lx - qx, qx - (lx + 63)));
                    int mdy = max(0, max(ly - qy, qy - (ly + 63)));
                    int mdz = max(0, max(lz - qz, qz - (lz + 63)));
                    int md2 = mdx * mdx + mdy * mdy + mdz * mdz;
                    if (md2 <= T) {
                        int cell = ci + GC * cj + GC * GC * ck;
                        ccnt = min(g_scr.cellcnt[cell], BCAP);
                        cbase = cell * BCAP;
                    }
                }
            }
            // warp inclusive scan of ccnt
            int inc = ccnt;
#pragma unroll
            for (int off = 1; off < 32; off <<= 1) {
                int v = __shfl_up_sync(FULL, inc, off);
                if (lane >= off) inc += v;
            }
            int P = __shfl_sync(FULL, inc, 31);
            if (P == 0) continue;
            if (lane == 0) s_pref[w][0] = 0;
            s_pref[w][lane + 1] = inc;
            s_base[w][lane] = cbase - (inc - ccnt);   // point = g_pts[base + t2]
            __syncwarp();

            // dual-batched scan: 64 points per iteration, independent LDG pair
            const int nb = (P + 31) >> 5;
            for (int it = 0; it < nb; it += 2) {
                int t2a = it * 32 + lane;
                int t2b = t2a + 32;
                bool va = (t2a < P), vb = (t2b < P);
                int ja = 0, jb = 0;
#pragma unroll
                for (int step = 16; step >= 1; step >>= 1) {
                    if (s_pref[w][ja + step] <= t2a) ja += step;
                    if (s_pref[w][jb + step] <= t2b) jb += step;
                }
                uint2 pa, pb;
                if (va) pa = g_pts[s_base[w][ja] + t2a];
                if (vb) pb = g_pts[s_base[w][jb] + t2b];
                int d2a = 0, d2b = 0;
                unsigned ia = 0, ib = 0;
                if (va) {
                    int dx = qx - (int)(pa.x & 0xffffu);
                    int dy = qy - (int)(pa.x >> 16);
                    int dz = qz - (int)(pa.y & 0xffffu);
                    d2a = dx * dx + dy * dy + dz * dz;
                    ia = pa.y >> 16;
                }
                if (vb) {
                    int dx = qx - (int)(pb.x & 0xffffu);
                    int dy = qy - (int)(pb.x >> 16);
                    int dz = qz - (int)(pb.y & 0xffffu);
                    d2b = dx * dx + dy * dy + dz * dz;
                    ib = pb.y >> 16;
                }
                bool ha = va && (d2a <= T);
                unsigned ma = __ballot_sync(FULL, ha);
                if (ha) s_buf[w][cnt + __popc(ma & lmlt)] = make_uint2((unsigned)d2a, ia);
                cnt += __popc(ma);
                bool hb = vb && (d2b <= T);
                unsigned mb = __ballot_sync(FULL, hb);
                if (hb) s_buf[w][cnt + __popc(mb & lmlt)] = make_uint2((unsigned)d2b, ib);
                cnt += __popc(mb);
                nearc += (ha && d2a <= NEAR2) + (hb && d2b <= NEAR2);
                if (cnt > CAP - 64) T = warp_prune(&s_buf[w][0], cnt, kk, lane);
            }
            __syncwarp();
        }
        // stage end
        if (first) {
            // fast completeness proof: >=k scanned points at d2<=NEAR2, and every
            // unscanned point has d2 > NEAR2 (min axis gap to shell-2 cell is 65).
            int C1 = __reduce_add_sync(FULL, nearc);
            if (C1 >= kk) { done = true; break; }
        }
        if (cnt >= kk) {
            T = warp_prune(&s_buf[w][0], cnt, kk, lane);
            int bnd = s << CSH;                  // next stage min d2 > (s*64)^2
            if (bnd * bnd >= T) done = true;
        }
    }

    // ----- final exact top-k by composite key (d2, idx): stable ties -----
    if (cnt > 32) T = warp_prune(&s_buf[w][0], cnt, kk, lane);  // compact to ~k+ties
    const int kk2 = min(kk, cnt);
    {
        uint2 e = (lane < cnt) ? s_buf[w][lane] : make_uint2(0xffffffffu, 0x7fffu);
        unsigned mxd2 = __reduce_max_sync(FULL, (lane < cnt) ? e.x : 0u);
        if (cnt <= 32 && mxd2 < (1u << 17)) {
            // 32-bit packed key: d2(<2^17) << 15 | idx(<2^15). Distinct idx ->
            // distinct keys -> dense unique ranks. Matches lax.top_k ordering.
            unsigned key = (e.x << 15) | (e.y & 0x7fffu);
            int rk = 0;
            for (int j = 0; j < cnt; j++) {
                unsigned kj = __shfl_sync(FULL, key, j);
                rk += (kj < key) ? 1 : 0;
            }
            if (lane < cnt && rk < kk2) {
                s_selidx[w][rk] = (int)e.y;
                s_seld2[w][rk]  = e.x;
            }
        } else {
            // cold exact fallback: smem-based rank count, no register arrays
            for (int i = lane; i < cnt; i += 32) {
                uint2 ei = s_buf[w][i];
                int rk = 0;
                for (int j = 0; j < cnt; j++) {
                    uint2 ej = s_buf[w][j];
                    rk += (ej.x < ei.x || (ej.x == ei.x && ej.y < ei.y)) ? 1 : 0;
                }
                if (rk < kk2) {
                    s_selidx[w][rk] = (int)ei.y;
                    s_seld2[w][rk]  = ei.x;
                }
            }
        }
        __syncwarp();
    }

    float wj = 0.0f;
    if (lane < kk2) wj = 1.0f / (1.0f + sqrtf((float)s_seld2[w][lane]));
    float tot = wj;
#pragma unroll
    for (int o = 16; o > 0; o >>= 1) tot += __shfl_xor_sync(FULL, tot, o);
    if (lane < kk2) s_wt[w][lane] = wj / tot;
    __syncwarp();

    // ----- weighted feature gather -----
    if (D == 128) {
        float4 acc = make_float4(0.f, 0.f, 0.f, 0.f);
        for (int j = 0; j < kk2; j++) {
            int   si = s_selidx[w][j];
            float wt = s_wt[w][j];
            const float* f = (si < M1) ? (midf + (size_t)si * 128)
                                       : (lowf + (size_t)(si - M1) * 128);
            float4 v = *(const float4*)(f + lane * 4);
            acc.x += wt * v.x; acc.y += wt * v.y;
            acc.z += wt * v.z; acc.w += wt * v.w;
        }
        *(float4*)(out + (size_t)q * 128 + lane * 4) = acc;
    } else {
        for (int d = lane; d < D; d += 32) {
            float a = 0.f;
            for (int j = 0; j < kk2; j++) {
                int   si = s_selidx[w][j];
                float wt = s_wt[w][j];
                const float* f = (si < M1) ? (midf + (size_t)si * D)
                                           : (lowf + (size_t)(si - M1) * D);
                a += wt * f[d];
            }
            out[(size_t)q * D + d] = a;
        }
    }
}

extern "C" void kernel_launch(void* const* d_in, const int* in_sizes, int n_in,
                              void* d_out, int out_size) {
    const int*   qc   = (const int*)d_in[0];
    const int*   midc = (const int*)d_in[1];
    const int*   lowc = (const int*)d_in[2];
    const float* midf = (const float*)d_in[3];
    const float* lowf = (const float*)d_in[4];
    const int*   kp   = (n_in >= 6) ? (const int*)d_in[5] : nullptr;

    const int N  = in_sizes[0] / 3;
    const int M1 = in_sizes[1] / 3;
    const int M2 = in_sizes[2] / 3;
    const int M  = M1 + M2;
    const int D  = (M1 > 0) ? in_sizes[3] / M1 : 128;

    void* scr = nullptr;
    cudaGetSymbolAddress(&scr, g_scr);             // host query, not a stream op
    cudaMemsetAsync(scr, 0, sizeof(Scratch));      // graph memset node

    build_kernel<<<(M + 255) / 256, 256>>>(midc, lowc, M1, M);
    knn_query_kernel<<<(N + QPB - 1) / QPB, 256>>>(qc, midf, lowf, kp,
                                                   (float*)d_out, N, M1, D);
}

// round 7
// speedup vs baseline: 1.4701x; 1.0132x over previous
#include <cuda_runtime.h>
#include <stdint.h>

#define QPB   8          // queries per block (1 per warp)
#define CAP   192        // candidate buffer per query (fallback path only fills it)
#define KMAX  32
#define MMAX  32768
#define GC    27         // grid cells per axis (1728/64)
#define NC    (GC*GC*GC) // 19683
#define CSH   6          // log2(cell size 64)
#define BCAP  32         // bucket capacity per cell
#define NEAR2 4096       // 64^2: any point outside cheb<=1 cube has d2 > NEAR2

// ---- device scratch (no allocs allowed) ----
struct Scratch {
    int ovcnt;
    int cellcnt[NC];
};
__device__ Scratch g_scr;            // zeroed by one cudaMemsetAsync per call
__device__ uint2 g_pts[NC * BCAP];   // bucketed: .x = x|y<<16, .y = z|idx<<16
__device__ uint2 g_ov[MMAX];         // overflow (exactness fallback; empty in practice)

__device__ __forceinline__ int cell_of(int x, int y, int z) {
    return (x >> CSH) + GC * (y >> CSH) + GC * GC * (z >> CSH);
}

__global__ void build_kernel(const int* __restrict__ mid, const int* __restrict__ low,
                             int M1, int M) {
    int i = blockIdx.x * blockDim.x + threadIdx.x;
    if (i >= M) return;
    const int* s = (i < M1) ? (mid + 3 * i) : (low + 3 * (i - M1));
    int x = s[0], y = s[1], z = s[2];
    int c = cell_of(x, y, z);
    uint2 pt = make_uint2((unsigned)x | ((unsigned)y << 16),
                          (unsigned)z | ((unsigned)i << 16));
    int pos = atomicAdd(&g_scr.cellcnt[c], 1);
    if (pos < BCAP) g_pts[c * BCAP + pos] = pt;
    else            g_ov[atomicAdd(&g_scr.ovcnt, 1)] = pt;
}

// Exact k-th select (binary search on integer d2), then compact entries with
// d2 <= T to front. Returns T; updates cnt (warp-uniform). Keeps all ties.
__device__ __forceinline__ int warp_prune(uint2* buf, int& cnt, int k, int lane) {
    const unsigned FULL = 0xffffffffu;
    unsigned d2r[CAP / 32], idr[CAP / 32];
#pragma unroll
    for (int s = 0; s < CAP / 32; s++) {
        int i = s * 32 + lane;
        uint2 e = (i < cnt) ? buf[i] : make_uint2(0x7fffffffu, 0u);
        d2r[s] = e.x; idr[s] = e.y;
    }
    unsigned mx = 0;
#pragma unroll
    for (int s = 0; s < CAP / 32; s++) {
        int i = s * 32 + lane;
        if (i < cnt) mx = max(mx, d2r[s]);
    }
    unsigned lo = 0, hi = __reduce_max_sync(FULL, mx);
    while (lo < hi) {
        unsigned mid = (lo + hi) >> 1;
        int c = 0;
#pragma unroll
        for (int s = 0; s < CAP / 32; s++) c += (d2r[s] <= mid) ? 1 : 0;
        c = __reduce_add_sync(FULL, c);
        if (c >= k) hi = mid; else lo = mid + 1;
    }
    unsigned T = lo;
    int base = 0;
#pragma unroll
    for (int s = 0; s < CAP / 32; s++) {
        bool keep = (d2r[s] <= T);
        unsigned m = __ballot_sync(FULL, keep);
        if (keep) buf[base + __popc(m & ((1u << lane) - 1u))] = make_uint2(d2r[s], idr[s]);
        base += __popc(m);
    }
    __syncwarp();
    cnt = base;
    return (int)T;
}

// Balanced segment-union scan of the cells owned by lanes (ccnt/cbase per lane).
// Appends hits with d2 <= T to bufrow; prunes (tightens T) on near-overflow.
__device__ __forceinline__ void scan_batch(int ccnt, int cbase,
                                           int qx, int qy, int qz,
                                           uint2* bufrow, int* prefrow, int* baserow,
                                           int& cnt, int& T, int kk,
                                           int lane, unsigned lmlt) {
    const unsigned FULL = 0xffffffffu;
    int inc = ccnt;
#pragma unroll
    for (int off = 1; off < 32; off <<= 1) {
        int v = __shfl_up_sync(FULL, inc, off);
        if (lane >= off) inc += v;
    }
    int P = __shfl_sync(FULL, inc, 31);
    if (P == 0) return;
    if (lane == 0) prefrow[0] = 0;
    prefrow[lane + 1] = inc;
    baserow[lane] = cbase - (inc - ccnt);       // point = g_pts[base + t2]
    __syncwarp();

    const int nb = (P + 31) >> 5;
    for (int it = 0; it < nb; it += 2) {
        int t2a = it * 32 + lane;
        int t2b = t2a + 32;
        bool va = (t2a < P), vb = (t2b < P);
        int ja = 0, jb = 0;
#pragma unroll
        for (int step = 16; step >= 1; step >>= 1) {
            if (prefrow[ja + step] <= t2a) ja += step;
            if (prefrow[jb + step] <= t2b) jb += step;
        }
        uint2 pa, pb;
        if (va) pa = g_pts[baserow[ja] + t2a];
        if (vb) pb = g_pts[baserow[jb] + t2b];
        int d2a = 0, d2b = 0;
        unsigned ia = 0, ib = 0;
        if (va) {
            int dx = qx - (int)(pa.x & 0xffffu);
            int dy = qy - (int)(pa.x >> 16);
            int dz = qz - (int)(pa.y & 0xffffu);
            d2a = dx * dx + dy * dy + dz * dz;
            ia = pa.y >> 16;
        }
        if (vb) {
            int dx = qx - (int)(pb.x & 0xffffu);
            int dy = qy - (int)(pb.x >> 16);
            int dz = qz - (int)(pb.y & 0xffffu);
            d2b = dx * dx + dy * dy + dz * dz;
            ib = pb.y >> 16;
        }
        bool ha = va && (d2a <= T);
        unsigned ma = __ballot_sync(FULL, ha);
        if (ha) bufrow[cnt + __popc(ma & lmlt)] = make_uint2((unsigned)d2a, ia);
        cnt += __popc(ma);
        bool hb = vb && (d2b <= T);
        unsigned mb = __ballot_sync(FULL, hb);
        if (hb) bufrow[cnt + __popc(mb & lmlt)] = make_uint2((unsigned)d2b, ib);
        cnt += __popc(mb);
        if (cnt > CAP - 64) T = min(T, warp_prune(bufrow, cnt, kk, lane));
    }
    __syncwarp();
}

__global__ __launch_bounds__(256)
void knn_query_kernel(const int* __restrict__ qc,
                      const float* __restrict__ midf,
                      const float* __restrict__ lowf,
                      const int* __restrict__ kp,
                      float* __restrict__ out,
                      int N, int M1, int D) {
    __shared__ uint2    s_buf[QPB][CAP];
    __shared__ int      s_base[QPB][32];
    __shared__ int      s_pref[QPB][33];
    __shared__ int      s_selidx[QPB][KMAX];
    __shared__ unsigned s_seld2[QPB][KMAX];
    __shared__ float    s_wt[QPB][KMAX];

    const unsigned FULL = 0xffffffffu;
    const int tid = threadIdx.x;
    const int w = tid >> 5;
    const int lane = tid & 31;
    const unsigned lmlt = (1u << lane) - 1u;
    const int kk = kp ? min(*kp, KMAX) : 24;

    const int q = blockIdx.x * QPB + w;
    if (q >= N) return;                         // whole warp exits together

    const int qx = qc[3 * q], qy = qc[3 * q + 1], qz = qc[3 * q + 2];
    const int qcx = min(qx >> CSH, GC - 1);
    const int qcy = min(qy >> CSH, GC - 1);
    const int qcz = min(qz >> CSH, GC - 1);

    int cnt = 0;

    // ============ PHASE 1 (common path): 27 cells, filter d2 <= NEAR2 ============
    // Proof: every point outside the cheb<=1 cube differs by >=2 cells on some
    // axis => axis distance >= 65 => d2 > 4096 = NEAR2. So if >= k points pass
    // the filter, the exact top-k is fully contained in this buffer.
    {
        int T1 = NEAR2;
        const int ov = g_scr.ovcnt;
        for (int b = 0; b < ov; b += 32) {       // overflow points (normally none)
            int i = b + lane;
            bool valid = (i < ov);
            int d2 = 0; unsigned pidx = 0;
            if (valid) {
                uint2 p = g_ov[i];
                int dx = qx - (int)(p.x & 0xffffu);
                int dy = qy - (int)(p.x >> 16);
                int dz = qz - (int)(p.y & 0xffffu);
                d2 = dx * dx + dy * dy + dz * dz;
                pidx = p.y >> 16;
            }
            bool hit = valid && (d2 <= T1);
            unsigned m = __ballot_sync(FULL, hit);
            if (hit) s_buf[w][cnt + __popc(m & lmlt)] = make_uint2((unsigned)d2, pidx);
            cnt += __popc(m);
            if (cnt > CAP - 32) warp_prune(&s_buf[w][0], cnt, kk, lane);
        }

        int ccnt = 0, cbase = 0;
        if (lane < 27) {
            int di = lane % 3 - 1;
            int dj = (lane / 3) % 3 - 1;
            int dk = lane / 9 - 1;
            int ci = qcx + di, cj = qcy + dj, ck = qcz + dk;
            if (ci >= 0 && ci < GC && cj >= 0 && cj < GC && ck >= 0 && ck < GC) {
                int lx = ci << CSH, ly = cj << CSH, lz = ck << CSH;
                int mdx = max(0, max(lx - qx, qx - (lx + 63)));
                int mdy = max(0, max(ly - qy, qy - (ly + 63)));
                int mdz = max(0, max(lz - qz, qz - (lz + 63)));
                if (mdx * mdx + mdy * mdy + mdz * mdz <= NEAR2) {
                    int cell = ci + GC * cj + GC * GC * ck;
                    ccnt = min(g_scr.cellcnt[cell], BCAP);
                    cbase = cell * BCAP;
                }
            }
        }
        scan_batch(ccnt, cbase, qx, qy, qz, &s_buf[w][0], &s_pref[w][0],
                   &s_base[w][0], cnt, T1, kk, lane, lmlt);
    }

    // ============ FALLBACK (sparse queries): unfiltered cube + shells ============
    if (cnt < kk) {
        cnt = 0;
        int T = 0x7fffffff;
        const int ov = g_scr.ovcnt;
        for (int b = 0; b < ov; b += 32) {
            int i = b + lane;
            bool valid = (i < ov);
            int d2 = 0; unsigned pidx = 0;
            if (valid) {
                uint2 p = g_ov[i];
                int dx = qx - (int)(p.x & 0xffffu);
                int dy = qy - (int)(p.x >> 16);
                int dz = qz - (int)(p.y & 0xffffu);
                d2 = dx * dx + dy * dy + dz * dz;
                pidx = p.y >> 16;
            }
            bool hit = valid && (d2 <= T);
            unsigned m = __ballot_sync(FULL, hit);
            if (hit) s_buf[w][cnt + __popc(m & lmlt)] = make_uint2((unsigned)d2, pidx);
            cnt += __popc(m);
            if (cnt > CAP - 32) T = warp_prune(&s_buf[w][0], cnt, kk, lane);
        }

        bool done = false;
        for (int s = 1; s < GC && !done; s++) {
            const int side = 2 * s + 1;
            const int ncube = side * side * side;
            const bool first = (s == 1);
            for (int b = 0; b < ncube; b += 32) {
                int t = b + lane;
                int ccnt = 0, cbase = 0;
                if (t < ncube) {
                    int di = t % side - s;
                    int r1 = t / side;
                    int dj = r1 % side - s;
                    int dk = r1 / side - s;
                    int cheb = max(abs(di), max(abs(dj), abs(dk)));
                    int ci = qcx + di, cj = qcy + dj, ck = qcz + dk;
                    if ((first || cheb == s) && ci >= 0 && ci < GC && cj >= 0
                                             && cj < GC && ck >= 0 && ck < GC) {
                        int lx = ci << CSH, ly = cj << CSH, lz = ck << CSH;
                        int mdx = max(0, max(lx - qx, qx - (lx + 63)));
                        int mdy = max(0, max(ly - qy, qy - (ly + 63)));
                        int mdz = max(0, max(lz - qz, qz - (lz + 63)));
                        int md2 = mdx * mdx + mdy * mdy + mdz * mdz;
                        if (md2 <= T) {
                            int cell = ci + GC * cj + GC * GC * ck;
                            ccnt = min(g_scr.cellcnt[cell], BCAP);
                            cbase = cell * BCAP;
                        }
                    }
                }
                scan_batch(ccnt, cbase, qx, qy, qz, &s_buf[w][0], &s_pref[w][0],
                           &s_base[w][0], cnt, T, kk, lane, lmlt);
            }
            if (cnt >= kk) {
                T = warp_prune(&s_buf[w][0], cnt, kk, lane);
                int bnd = s << CSH;              // next stage min d2 > (s*64)^2
                if (bnd * bnd >= T) done = true;
            }
        }
    }

    // ----- final exact top-k by composite key (d2, idx): stable ties -----
    if (cnt > 32) warp_prune(&s_buf[w][0], cnt, kk, lane);   // compact to ~k+ties
    const int kk2 = min(kk, cnt);
    {
        uint2 e = (lane < cnt) ? s_buf[w][lane] : make_uint2(0xffffffffu, 0x7fffu);
        unsigned mxd2 = __reduce_max_sync(FULL, (lane < cnt) ? e.x : 0u);
        if (cnt <= 32 && mxd2 < (1u << 17)) {
            // 32-bit packed key: d2(<2^17) << 15 | idx(<2^15). Distinct idx ->
            // distinct keys -> dense unique ranks. Matches lax.top_k ordering.
            unsigned key = (e.x << 15) | (e.y & 0x7fffu);
            int rk = 0;
            for (int j = 0; j < cnt; j++) {
                unsigned kj = __shfl_sync(FULL, key, j);
                rk += (kj < key) ? 1 : 0;
            }
            if (lane < cnt && rk < kk2) {
                s_selidx[w][rk] = (int)e.y;
                s_seld2[w][rk]  = e.x;
            }
        } else {
            // cold exact fallback: smem-based rank count
            for (int i = lane; i < cnt; i += 32) {
                uint2 ei = s_buf[w][i];
                int rk = 0;
                for (int j = 0; j < cnt; j++) {
                    uint2 ej = s_buf[w][j];
                    rk += (ej.x < ei.x || (ej.x == ei.x && ej.y < ei.y)) ? 1 : 0;
                }
                if (rk < kk2) {
                    s_selidx[w][rk] = (int)ei.y;
                    s_seld2[w][rk]  = ei.x;
                }
            }
        }
        __syncwarp();
    }

    float wj = 0.0f;
    if (lane < kk2) wj = 1.0f / (1.0f + sqrtf((float)s_seld2[w][lane]));
    float tot = wj;
#pragma unroll
    for (int o = 16; o > 0; o >>= 1) tot += __shfl_xor_sync(FULL, tot, o);
    if (lane < kk2) s_wt[w][lane] = wj / tot;
    __syncwarp();

    // ----- weighted feature gather -----
    if (D == 128) {
        float4 acc = make_float4(0.f, 0.f, 0.f, 0.f);
        for (int j = 0; j < kk2; j++) {
            int   si = s_selidx[w][j];
            float wt = s_wt[w][j];
            const float* f = (si < M1) ? (midf + (size_t)si * 128)
                                       : (lowf + (size_t)(si - M1) * 128);
            float4 v = *(const float4*)(f + lane * 4);
            acc.x += wt * v.x; acc.y += wt * v.y;
            acc.z += wt * v.z; acc.w += wt * v.w;
        }
        *(float4*)(out + (size_t)q * 128 + lane * 4) = acc;
    } else {
        for (int d = lane; d < D; d += 32) {
            float a = 0.f;
            for (int j = 0; j < kk2; j++) {
                int   si = s_selidx[w][j];
                float wt = s_wt[w][j];
                const float* f = (si < M1) ? (midf + (size_t)si * D)
                                           : (lowf + (size_t)(si - M1) * D);
                a += wt * f[d];
            }
            out[(size_t)q * D + d] = a;
        }
    }
}

extern "C" void kernel_launch(void* const* d_in, const int* in_sizes, int n_in,
                              void* d_out, int out_size) {
    const int*   qc   = (const int*)d_in[0];
    const int*   midc = (const int*)d_in[1];
    const int*   lowc = (const int*)d_in[2];
    const float* midf = (const float*)d_in[3];
    const float* lowf = (const float*)d_in[4];
    const int*   kp   = (n_in >= 6) ? (const int*)d_in[5] : nullptr;

    const int N  = in_sizes[0] / 3;
    const int M1 = in_sizes[1] / 3;
    const int M2 = in_sizes[2] / 3;
    const int M  = M1 + M2;
    const int D  = (M1 > 0) ? in_sizes[3] / M1 : 128;

    void* scr = nullptr;
    cudaGetSymbolAddress(&scr, g_scr);             // host query, not a stream op
    cudaMemsetAsync(scr, 0, sizeof(Scratch));      // graph memset node

    build_kernel<<<(M + 255) / 256, 256>>>(midc, lowc, M1, M);
    knn_query_kernel<<<(N + QPB - 1) / QPB, 256>>>(qc, midf, lowf, kp,
                                                   (float*)d_out, N, M1, D);
}

// round 8
// speedup vs baseline: 1.5994x; 1.0880x over previous
#include <cuda_runtime.h>
#include <stdint.h>

#define QPB   4          // queries per block (1 per warp)
#define CAP   192        // candidate buffer per query
#define KMAX  32
#define MMAX  32768
#define GC    27         // grid cells per axis (1728/64)
#define NC    (GC*GC*GC) // 19683
#define CSH   6          // log2(cell size 64)
#define BCAP  32         // bucket capacity per cell
#define NEAR2 4096       // 64^2: any point outside cheb<=1 cube has d2 > NEAR2

// ---- device scratch (no allocs allowed) ----
struct Scratch {
    int ovcnt;
    int cellcnt[NC];
};
__device__ Scratch g_scr;            // zeroed by one cudaMemsetAsync per call
__device__ uint2 g_pts[NC * BCAP];   // bucketed: .x = x|y<<16, .y = z|idx<<16
__device__ uint2 g_ov[MMAX];         // overflow (exactness fallback; empty in practice)

__device__ __forceinline__ int cell_of(int x, int y, int z) {
    return (x >> CSH) + GC * (y >> CSH) + GC * GC * (z >> CSH);
}

__global__ void build_kernel(const int* __restrict__ mid, const int* __restrict__ low,
                             int M1, int M) {
    int i = blockIdx.x * blockDim.x + threadIdx.x;
    if (i >= M) return;
    const int* s = (i < M1) ? (mid + 3 * i) : (low + 3 * (i - M1));
    int x = s[0], y = s[1], z = s[2];
    int c = cell_of(x, y, z);
    uint2 pt = make_uint2((unsigned)x | ((unsigned)y << 16),
                          (unsigned)z | ((unsigned)i << 16));
    int pos = atomicAdd(&g_scr.cellcnt[c], 1);
    if (pos < BCAP) g_pts[c * BCAP + pos] = pt;
    else            g_ov[atomicAdd(&g_scr.ovcnt, 1)] = pt;
}

// Exact k-th select (binary search on integer d2), then compact entries with
// d2 <= T to front. Returns T; updates cnt (warp-uniform). Keeps all ties.
__device__ __forceinline__ int warp_prune(uint2* buf, int& cnt, int k, int lane) {
    const unsigned FULL = 0xffffffffu;
    unsigned d2r[CAP / 32], idr[CAP / 32];
#pragma unroll
    for (int s = 0; s < CAP / 32; s++) {
        int i = s * 32 + lane;
        uint2 e = (i < cnt) ? buf[i] : make_uint2(0x7fffffffu, 0u);
        d2r[s] = e.x; idr[s] = e.y;
    }
    unsigned mx = 0;
#pragma unroll
    for (int s = 0; s < CAP / 32; s++) {
        int i = s * 32 + lane;
        if (i < cnt) mx = max(mx, d2r[s]);
    }
    unsigned lo = 0, hi = __reduce_max_sync(FULL, mx);
    while (lo < hi) {
        unsigned mid = (lo + hi) >> 1;
        int c = 0;
#pragma unroll
        for (int s = 0; s < CAP / 32; s++) c += (d2r[s] <= mid) ? 1 : 0;
        c = __reduce_add_sync(FULL, c);
        if (c >= k) hi = mid; else lo = mid + 1;
    }
    unsigned T = lo;
    int base = 0;
#pragma unroll
    for (int s = 0; s < CAP / 32; s++) {
        bool keep = (d2r[s] <= T);
        unsigned m = __ballot_sync(FULL, keep);
        if (keep) buf[base + __popc(m & ((1u << lane) - 1u))] = make_uint2(d2r[s], idr[s]);
        base += __popc(m);
    }
    __syncwarp();
    cnt = base;
    return (int)T;
}

// Balanced segment-union scan (fallback path): dual-batched, ballot append.
__device__ __forceinline__ void scan_batch(int ccnt, int cbase,
                                           int qx, int qy, int qz,
                                           uint2* bufrow, int* prefrow, int* baserow,
                                           int& cnt, int& T, int kk,
                                           int lane, unsigned lmlt) {
    const unsigned FULL = 0xffffffffu;
    int inc = ccnt;
#pragma unroll
    for (int off = 1; off < 32; off <<= 1) {
        int v = __shfl_up_sync(FULL, inc, off);
        if (lane >= off) inc += v;
    }
    int P = __shfl_sync(FULL, inc, 31);
    if (P == 0) return;
    if (lane == 0) prefrow[0] = 0;
    prefrow[lane + 1] = inc;
    baserow[lane] = cbase - (inc - ccnt);
    __syncwarp();

    const int nb = (P + 31) >> 5;
    for (int it = 0; it < nb; it += 2) {
        int t2a = it * 32 + lane;
        int t2b = t2a + 32;
        bool va = (t2a < P), vb = (t2b < P);
        int ja = 0, jb = 0;
#pragma unroll
        for (int step = 16; step >= 1; step >>= 1) {
            if (prefrow[ja + step] <= t2a) ja += step;
            if (prefrow[jb + step] <= t2b) jb += step;
        }
        uint2 pa, pb;
        if (va) pa = g_pts[baserow[ja] + t2a];
        if (vb) pb = g_pts[baserow[jb] + t2b];
        int d2a = 0, d2b = 0;
        unsigned ia = 0, ib = 0;
        if (va) {
            int dx = qx - (int)(pa.x & 0xffffu);
            int dy = qy - (int)(pa.x >> 16);
            int dz = qz - (int)(pa.y & 0xffffu);
            d2a = dx * dx + dy * dy + dz * dz;
            ia = pa.y >> 16;
        }
        if (vb) {
            int dx = qx - (int)(pb.x & 0xffffu);
            int dy = qy - (int)(pb.x >> 16);
            int dz = qz - (int)(pb.y & 0xffffu);
            d2b = dx * dx + dy * dy + dz * dz;
            ib = pb.y >> 16;
        }
        bool ha = va && (d2a <= T);
        unsigned ma = __ballot_sync(FULL, ha);
        if (ha) bufrow[cnt + __popc(ma & lmlt)] = make_uint2((unsigned)d2a, ia);
        cnt += __popc(ma);
        bool hb = vb && (d2b <= T);
        unsigned mb = __ballot_sync(FULL, hb);
        if (hb) bufrow[cnt + __popc(mb & lmlt)] = make_uint2((unsigned)d2b, ib);
        cnt += __popc(mb);
        if (cnt > CAP - 64) T = min(T, warp_prune(bufrow, cnt, kk, lane));
    }
    __syncwarp();
}

__global__ __launch_bounds__(128)
void knn_query_kernel(const int* __restrict__ qc,
                      const float* __restrict__ midf,
                      const float* __restrict__ lowf,
                      const int* __restrict__ kp,
                      float* __restrict__ out,
                      int N, int M1, int D) {
    __shared__ uint2    s_buf[QPB][CAP];
    __shared__ int      s_cbase[QPB][32];
    __shared__ int      s_ccnt[QPB][32];
    __shared__ int      s_pref[QPB][33];
    __shared__ int      s_selidx[QPB][KMAX];
    __shared__ unsigned s_seld2[QPB][KMAX];
    __shared__ float    s_wt[QPB][KMAX];

    const unsigned FULL = 0xffffffffu;
    const int tid = threadIdx.x;
    const int w = tid >> 5;
    const int lane = tid & 31;
    const unsigned lmlt = (1u << lane) - 1u;
    const int kk = kp ? min(*kp, KMAX) : 24;

    const int q = blockIdx.x * QPB + w;
    if (q >= N) return;                         // whole warp exits together

    const int qx = qc[3 * q], qy = qc[3 * q + 1], qz = qc[3 * q + 2];
    const int qcx = min(qx >> CSH, GC - 1);
    const int qcy = min(qy >> CSH, GC - 1);
    const int qcz = min(qz >> CSH, GC - 1);

    int cnt = 0;
    const int ov = g_scr.ovcnt;

    // ============ PHASE 1 (common): 27 cells, chunk-of-4 scan, d2 <= NEAR2 ======
    // Proof: every point outside the cheb<=1 cube has axis gap >= 65 => d2 > 4096.
    // If >= k points pass, the exact top-k is contained in the buffer.
    {
        int ccnt = 0, cbase = 0;
        if (lane < 27) {
            int di = lane % 3 - 1;
            int dj = (lane / 3) % 3 - 1;
            int dk = lane / 9 - 1;
            int ci = qcx + di, cj = qcy + dj, ck = qcz + dk;
            if (ci >= 0 && ci < GC && cj >= 0 && cj < GC && ck >= 0 && ck < GC) {
                int cell = ci + GC * cj + GC * GC * ck;
                ccnt = min(g_scr.cellcnt[cell], BCAP);
                cbase = cell * BCAP;
            }
        }
        int P = __reduce_add_sync(FULL, ccnt);
        if (ov == 0 && P >= kk) {
            s_cbase[w][lane] = cbase;
            s_ccnt[w][lane]  = ccnt;
            int ch = (ccnt + 3) >> 2;           // 4-point chunks per cell
            int inc = ch;
#pragma unroll
            for (int off = 1; off < 32; off <<= 1) {
                int v = __shfl_up_sync(FULL, inc, off);
                if (lane >= off) inc += v;
            }
            int CH = __shfl_sync(FULL, inc, 31);
            if (lane == 0) s_pref[w][0] = 0;
            s_pref[w][lane + 1] = inc;
            __syncwarp();

            int T1 = NEAR2;
            for (int c0 = 0; c0 < CH; c0 += 32) {
                int c2 = c0 + lane;
                bool cv = (c2 < CH);
                int c2c = cv ? c2 : 0;
                int j = 0;
#pragma unroll
                for (int step = 16; step >= 1; step >>= 1)
                    if (s_pref[w][j + step] <= c2c) j += step;
                int base = s_cbase[w][j];
                int cc   = s_ccnt[w][j];
                int off4 = (c2c - s_pref[w][j]) << 2;
                int nv   = cv ? min(4, cc - off4) : 0;
                uint4 A = make_uint4(0, 0, 0, 0), B = make_uint4(0, 0, 0, 0);
                if (cv) {
                    const uint4* p4 = reinterpret_cast<const uint4*>(&g_pts[base + off4]);
                    A = p4[0];                 // entries 0,1 (always in-bucket)
                    B = p4[1];                 // entries 2,3 (in-bucket: off4+3 < BCAP)
                }
                unsigned px[4] = {A.x, A.z, B.x, B.z};
                unsigned pz[4] = {A.y, A.w, B.y, B.w};
#pragma unroll
                for (int u = 0; u < 4; u++) {
                    int d2 = 0;
                    unsigned pidx = 0;
                    bool valid = (u < nv);
                    if (valid) {
                        int dx = qx - (int)(px[u] & 0xffffu);
                        int dy = qy - (int)(px[u] >> 16);
                        int dz = qz - (int)(pz[u] & 0xffffu);
                        d2 = dx * dx + dy * dy + dz * dz;
                        pidx = pz[u] >> 16;
                    }
                    bool hit = valid && (d2 <= T1);
                    unsigned m = __ballot_sync(FULL, hit);
                    if (hit) s_buf[w][cnt + __popc(m & lmlt)] =
                                 make_uint2((unsigned)d2, pidx);
                    cnt += __popc(m);
                }
                if (cnt > 64) T1 = min(T1, warp_prune(&s_buf[w][0], cnt, kk, lane));
            }
        }
    }

    // ============ FALLBACK (sparse / overflow): unfiltered cube + shells ========
    if (cnt < kk) {
        cnt = 0;
        int T = 0x7fffffff;
        for (int b = 0; b < ov; b += 32) {
            int i = b + lane;
            bool valid = (i < ov);
            int d2 = 0; unsigned pidx = 0;
            if (valid) {
                uint2 p = g_ov[i];
                int dx = qx - (int)(p.x & 0xffffu);
                int dy = qy - (int)(p.x >> 16);
                int dz = qz - (int)(p.y & 0xffffu);
                d2 = dx * dx + dy * dy + dz * dz;
                pidx = p.y >> 16;
            }
            bool hit = valid && (d2 <= T);
            unsigned m = __ballot_sync(FULL, hit);
            if (hit) s_buf[w][cnt + __popc(m & lmlt)] = make_uint2((unsigned)d2, pidx);
            cnt += __popc(m);
            if (cnt > CAP - 32) T = warp_prune(&s_buf[w][0], cnt, kk, lane);
        }

        bool done = false;
        for (int s = 1; s < GC && !done; s++) {
            const int side = 2 * s + 1;
            const int ncube = side * side * side;
            const bool first = (s == 1);
            for (int b = 0; b < ncube; b += 32) {
                int t = b + lane;
                int ccnt = 0, cbase = 0;
                if (t < ncube) {
                    int di = t % side - s;
                    int r1 = t / side;
                    int dj = r1 % side - s;
                    int dk = r1 / side - s;
                    int cheb = max(abs(di), max(abs(dj), abs(dk)));
                    int ci = qcx + di, cj = qcy + dj, ck = qcz + dk;
                    if ((first || cheb == s) && ci >= 0 && ci < GC && cj >= 0
                                             && cj < GC && ck >= 0 && ck < GC) {
                        int lx = ci << CSH, ly = cj << CSH, lz = ck << CSH;
                        int mdx = max(0, max(lx - qx, qx - (lx + 63)));
                        int mdy = max(0, max(ly - qy, qy - (ly + 63)));
                        int mdz = max(0, max(lz - qz, qz - (lz + 63)));
                        int md2 = mdx * mdx + mdy * mdy + mdz * mdz;
                        if (md2 <= T) {
                            int cell = ci + GC * cj + GC * GC * ck;
                            ccnt = min(g_scr.cellcnt[cell], BCAP);
                            cbase = cell * BCAP;
                        }
                    }
                }
                scan_batch(ccnt, cbase, qx, qy, qz, &s_buf[w][0], &s_pref[w][0],
                           &s_cbase[w][0], cnt, T, kk, lane, lmlt);
            }
            if (cnt >= kk) {
                T = warp_prune(&s_buf[w][0], cnt, kk, lane);
                int bnd = s << CSH;              // next stage min d2 > (s*64)^2
                if (bnd * bnd >= T) done = true;
            }
        }
    }

    // ----- final exact top-k by composite key (d2, idx): stable ties -----
    if (cnt > 64) warp_prune(&s_buf[w][0], cnt, kk, lane);   // rare: compact first
    const int kk2 = min(kk, cnt);
    {
        bool v0 = (lane < cnt), v1 = (lane + 32 < cnt);
        uint2 e0 = v0 ? s_buf[w][lane]      : make_uint2(0u, 0u);
        uint2 e1 = v1 ? s_buf[w][lane + 32] : make_uint2(0u, 0u);
        unsigned mxd2 = __reduce_max_sync(FULL, max(v0 ? e0.x : 0u, v1 ? e1.x : 0u));
        if (cnt <= 64 && mxd2 < (1u << 17)) {
            // 32-bit packed key: d2(<2^17) << 15 | idx(<2^15); ascending order ==
            // (d2, idx) lexicographic == lax.top_k stable order.
            unsigned k0 = v0 ? ((e0.x << 15) | (e0.y & 0x7fffu)) : 0xffffffffu;
            unsigned k1 = v1 ? ((e1.x << 15) | (e1.y & 0x7fffu)) : 0xffffffffu;
            if (cnt <= 32) {
                int r0 = 0;
                for (int j = 0; j < 32; j++) {
                    unsigned a = __shfl_sync(FULL, k0, j);
                    r0 += (a < k0) ? 1 : 0;
                }
                if (v0 && r0 < kk2) { s_selidx[w][r0] = (int)e0.y; s_seld2[w][r0] = e0.x; }
            } else {
                int r0 = 0, r1 = 0;
                for (int j = 0; j < 32; j++) {
                    unsigned a = __shfl_sync(FULL, k0, j);
                    unsigned b = __shfl_sync(FULL, k1, j);
                    r0 += ((a < k0) ? 1 : 0) + ((b < k0) ? 1 : 0);
                    r1 += ((a < k1) ? 1 : 0) + ((b < k1) ? 1 : 0);
                }
                if (v0 && r0 < kk2) { s_selidx[w][r0] = (int)e0.y; s_seld2[w][r0] = e0.x; }
                if (v1 && r1 < kk2) { s_selidx[w][r1] = (int)e1.y; s_seld2[w][r1] = e1.x; }
            }
        } else {
            // cold exact fallback: smem-based rank count
            for (int i = lane; i < cnt; i += 32) {
                uint2 ei = s_buf[w][i];
                int rk = 0;
                for (int j = 0; j < cnt; j++) {
                    uint2 ej = s_buf[w][j];
                    rk += (ej.x < ei.x || (ej.x == ei.x && ej.y < ei.y)) ? 1 : 0;
                }
                if (rk < kk2) { s_selidx[w][rk] = (int)ei.y; s_seld2[w][rk] = ei.x; }
            }
        }
        __syncwarp();
    }

    float wj = 0.0f;
    if (lane < kk2) wj = 1.0f / (1.0f + sqrtf((float)s_seld2[w][lane]));
    float tot = wj;
#pragma unroll
    for (int o = 16; o > 0; o >>= 1) tot += __shfl_xor_sync(FULL, tot, o);
    if (lane < kk2) s_wt[w][lane] = wj / tot;
    __syncwarp();

    // ----- weighted feature gather (unroll-4 for MLP) -----
    if (D == 128) {
        float4 acc = make_float4(0.f, 0.f, 0.f, 0.f);
        int j = 0;
        for (; j + 4 <= kk2; j += 4) {
            const float* f[4];
            float wt[4];
#pragma unroll
            for (int u = 0; u < 4; u++) {
                int si = s_selidx[w][j + u];
                wt[u] = s_wt[w][j + u];
                f[u] = (si < M1) ? (midf + (size_t)si * 128)
                                 : (lowf + (size_t)(si - M1) * 128);
            }
            float4 v0 = *(const float4*)(f[0] + lane * 4);
            float4 v1 = *(const float4*)(f[1] + lane * 4);
            float4 v2 = *(const float4*)(f[2] + lane * 4);
            float4 v3 = *(const float4*)(f[3] + lane * 4);
            acc.x += wt[0] * v0.x + wt[1] * v1.x + wt[2] * v2.x + wt[3] * v3.x;
            acc.y += wt[0] * v0.y + wt[1] * v1.y + wt[2] * v2.y + wt[3] * v3.y;
            acc.z += wt[0] * v0.z + wt[1] * v1.z + wt[2] * v2.z + wt[3] * v3.z;
            acc.w += wt[0] * v0.w + wt[1] * v1.w + wt[2] * v2.w + wt[3] * v3.w;
        }
        for (; j < kk2; j++) {
            int   si = s_selidx[w][j];
            float wt = s_wt[w][j];
            const float* f = (si < M1) ? (midf + (size_t)si * 128)
                                       : (lowf + (size_t)(si - M1) * 128);
            float4 v = *(const float4*)(f + lane * 4);
            acc.x += wt * v.x; acc.y += wt * v.y;
            acc.z += wt * v.z; acc.w += wt * v.w;
        }
        *(float4*)(out + (size_t)q * 128 + lane * 4) = acc;
    } else {
        for (int d = lane; d < D; d += 32) {
            float a = 0.f;
            for (int j = 0; j < kk2; j++) {
                int   si = s_selidx[w][j];
                float wt = s_wt[w][j];
                const float* f = (si < M1) ? (midf + (size_t)si * D)
                                           : (lowf + (size_t)(si - M1) * D);
                a += wt * f[d];
            }
            out[(size_t)q * D + d] = a;
        }
    }
}

extern "C" void kernel_launch(void* const* d_in, const int* in_sizes, int n_in,
                              void* d_out, int out_size) {
    const int*   qc   = (const int*)d_in[0];
    const int*   midc = (const int*)d_in[1];
    const int*   lowc = (const int*)d_in[2];
    const float* midf = (const float*)d_in[3];
    const float* lowf = (const float*)d_in[4];
    const int*   kp   = (n_in >= 6) ? (const int*)d_in[5] : nullptr;

    const int N  = in_sizes[0] / 3;
    const int M1 = in_sizes[1] / 3;
    const int M2 = in_sizes[2] / 3;
    const int M  = M1 + M2;
    const int D  = (M1 > 0) ? in_sizes[3] / M1 : 128;

    void* scr = nullptr;
    cudaGetSymbolAddress(&scr, g_scr);             // host query, not a stream op
    cudaMemsetAsync(scr, 0, sizeof(Scratch));      // graph memset node

    build_kernel<<<(M + 255) / 256, 256>>>(midc, lowc, M1, M);
    knn_query_kernel<<<(N + QPB - 1) / QPB, 128>>>(qc, midf, lowf, kp,
                                                   (float*)d_out, N, M1, D);
}